// round 3
// baseline (speedup 1.0000x reference)
#include <cuda_runtime.h>
#include <math.h>
#include <stdint.h>

#define D_MODEL   1024
#define D_STATE   16
#define D_CONV    4
#define D_INNER   2048
#define DT_RANK   64
#define IN_SIZE   512
#define OUT_SIZE  512
#define BATCH     2048
#define XDB_COLS  96
#define STATE_W   20

// ---------------- scratch ----------------
__device__ float g_h[BATCH * D_MODEL];
__device__ float g_xz[BATCH * 2 * D_INNER];
__device__ float g_xc[BATCH * D_INNER];
__device__ float g_xdb[BATCH * XDB_COLS];
__device__ float g_dt[BATCH * D_INNER];
__device__ float g_y[BATCH * D_INNER];
__device__ float g_core[BATCH * D_MODEL];
// tf32 hi/lo split buffers (reused serially across GEMMs)
__device__ uint32_t g_Ahi[2048 * 2048];
__device__ uint32_t g_Alo[2048 * 2048];
__device__ uint32_t g_Bhi[4096 * 1024];
__device__ uint32_t g_Blo[4096 * 1024];

// ---------------- helpers ----------------
__device__ __forceinline__ float softplusf(float x) {
    return (x > 0.f) ? (x + log1pf(__expf(-x))) : log1pf(__expf(x));
}
__device__ __forceinline__ float siluf(float x) {
    return x / (1.f + __expf(-x));
}
__device__ __forceinline__ uint32_t f2tf(float x) {
    uint32_t r;
    asm("cvt.rna.tf32.f32 %0, %1;" : "=r"(r) : "f"(x));
    return r;
}
__device__ __forceinline__ void mma8(float* c, const uint32_t* a, const uint32_t* b) {
    asm volatile(
        "mma.sync.aligned.m16n8k8.row.col.f32.tf32.tf32.f32 "
        "{%0,%1,%2,%3}, {%4,%5,%6,%7}, {%8,%9}, {%0,%1,%2,%3};"
        : "+f"(c[0]), "+f"(c[1]), "+f"(c[2]), "+f"(c[3])
        : "r"(a[0]), "r"(a[1]), "r"(a[2]), "r"(a[3]), "r"(b[0]), "r"(b[1]));
}
__device__ __forceinline__ void cpa16(uint32_t dst, const uint32_t* src, bool p) {
    int sz = p ? 16 : 0;
    asm volatile("cp.async.cg.shared.global [%0], [%1], 16, %2;\n"
                 :: "r"(dst), "l"(src), "r"(sz));
}

// ---------------- tf32 hi/lo split pass ----------------
__global__ void __launch_bounds__(256)
split_kernel(const float* __restrict__ in, uint32_t* __restrict__ hi,
             uint32_t* __restrict__ lo, int n4)
{
    int i = blockIdx.x * 256 + threadIdx.x;
    if (i < n4) {
        float4 v = reinterpret_cast<const float4*>(in)[i];
        uint4 h, l;
        h.x = f2tf(v.x); l.x = f2tf(v.x - __uint_as_float(h.x));
        h.y = f2tf(v.y); l.y = f2tf(v.y - __uint_as_float(h.y));
        h.z = f2tf(v.z); l.z = f2tf(v.z - __uint_as_float(h.z));
        h.w = f2tf(v.w); l.w = f2tf(v.w - __uint_as_float(h.w));
        reinterpret_cast<uint4*>(hi)[i] = h;
        reinterpret_cast<uint4*>(lo)[i] = l;
    }
}

// ======================================================================
// 3xTF32 tensor GEMM, pre-split operands, cp.async double-buffered.
// C[M,N] = A[M,K] * op(B). TB: B is NxK. !TB: B is KxN.
// BM=BN=128, BK=32, 256 thr, warps 4(m)x2(n), warp tile 32x64.
// EPI: 0 none, 1 +bias, 2 +bias+softplus. SPLITK: atomicAdd + N-guard.
// ======================================================================
template<bool TB, int EPI, bool SPLITK>
__global__ void __launch_bounds__(256, 1)
tgemm2(const uint32_t* __restrict__ Ahi, const uint32_t* __restrict__ Alo,
       const uint32_t* __restrict__ Bhi, const uint32_t* __restrict__ Blo,
       float* __restrict__ C, const float* __restrict__ bias,
       int M, int N, int K, int lda, int ldb, int ldc)
{
    extern __shared__ uint32_t smbuf[];
    constexpr int ASZ = 128 * 36;
    constexpr int BSZ = TB ? 128 * 36 : 32 * 132;
    constexpr int BLD = TB ? 36 : 132;
    constexpr int STAGE = 2 * ASZ + 2 * BSZ;

    const int tid  = threadIdx.x;
    const int lane = tid & 31;
    const int warp = tid >> 5;
    const int wm   = warp & 3;
    const int wn   = warp >> 2;
    const int m0   = blockIdx.y * 128;
    const int n0   = blockIdx.x * 128;
    const int Kc   = SPLITK ? (K / gridDim.z) : K;
    const int k0b  = SPLITK ? (blockIdx.z * Kc) : 0;
    const int T    = Kc / 32;

    const int ar = tid >> 3;             // 0..31
    const int ac = (tid & 7) * 4;        // 0..28
    const int br = TB ? (tid >> 3) : (tid >> 5);
    const int bc = TB ? ((tid & 7) * 4) : ((tid & 31) * 4);

    float acc[2][8][4];
#pragma unroll
    for (int i = 0; i < 2; i++)
#pragma unroll
        for (int j = 0; j < 8; j++)
#pragma unroll
            for (int q = 0; q < 4; q++) acc[i][j][q] = 0.f;

    auto fill = [&](int t, int st) {
        uint32_t* Ah = smbuf + st * STAGE;
        uint32_t* Al = Ah + ASZ;
        uint32_t* Bh = Al + ASZ;
        uint32_t* Bl = Bh + BSZ;
        const int k0 = k0b + t * 32;
#pragma unroll
        for (int it = 0; it < 4; it++) {
            const int row = ar + it * 32;
            const size_t g = (size_t)(m0 + row) * lda + k0 + ac;
            cpa16((uint32_t)__cvta_generic_to_shared(&Ah[row * 36 + ac]), Ahi + g, true);
            cpa16((uint32_t)__cvta_generic_to_shared(&Al[row * 36 + ac]), Alo + g, true);
        }
        if (TB) {
#pragma unroll
            for (int it = 0; it < 4; it++) {
                const int row = br + it * 32;
                const bool p = SPLITK ? ((n0 + row) < N) : true;
                const size_t g = (size_t)(n0 + row) * ldb + k0 + bc;
                cpa16((uint32_t)__cvta_generic_to_shared(&Bh[row * 36 + bc]), Bhi + g, p);
                cpa16((uint32_t)__cvta_generic_to_shared(&Bl[row * 36 + bc]), Blo + g, p);
            }
        } else {
#pragma unroll
            for (int it = 0; it < 4; it++) {
                const int row = br + it * 8;
                const size_t g = (size_t)(k0 + row) * ldb + n0 + bc;
                cpa16((uint32_t)__cvta_generic_to_shared(&Bh[row * 132 + bc]), Bhi + g, true);
                cpa16((uint32_t)__cvta_generic_to_shared(&Bl[row * 132 + bc]), Blo + g, true);
            }
        }
    };

    auto compute = [&](int st) {
        uint32_t* Ah = smbuf + st * STAGE;
        uint32_t* Al = Ah + ASZ;
        uint32_t* Bh = Al + ASZ;
        uint32_t* Bl = Bh + BSZ;
#pragma unroll
        for (int ks = 0; ks < 32; ks += 8) {
            uint32_t ah[2][4], al[2][4];
#pragma unroll
            for (int mt = 0; mt < 2; mt++) {
                const int mr = wm * 32 + mt * 16 + (lane >> 2);
                const int kc = ks + (lane & 3);
                ah[mt][0] = Ah[mr * 36 + kc];
                ah[mt][1] = Ah[(mr + 8) * 36 + kc];
                ah[mt][2] = Ah[mr * 36 + kc + 4];
                ah[mt][3] = Ah[(mr + 8) * 36 + kc + 4];
                al[mt][0] = Al[mr * 36 + kc];
                al[mt][1] = Al[(mr + 8) * 36 + kc];
                al[mt][2] = Al[mr * 36 + kc + 4];
                al[mt][3] = Al[(mr + 8) * 36 + kc + 4];
            }
            uint32_t bh[8][2], bl[8][2];
#pragma unroll
            for (int nt = 0; nt < 8; nt++) {
                const int nc = wn * 64 + nt * 8 + (lane >> 2);
                const int kc = ks + (lane & 3);
                if (TB) {
                    bh[nt][0] = Bh[nc * BLD + kc];
                    bh[nt][1] = Bh[nc * BLD + kc + 4];
                    bl[nt][0] = Bl[nc * BLD + kc];
                    bl[nt][1] = Bl[nc * BLD + kc + 4];
                } else {
                    bh[nt][0] = Bh[kc * BLD + nc];
                    bh[nt][1] = Bh[(kc + 4) * BLD + nc];
                    bl[nt][0] = Bl[kc * BLD + nc];
                    bl[nt][1] = Bl[(kc + 4) * BLD + nc];
                }
            }
#pragma unroll
            for (int mt = 0; mt < 2; mt++)
#pragma unroll
                for (int nt = 0; nt < 8; nt++) {
                    mma8(acc[mt][nt], al[mt], bh[nt]);
                    mma8(acc[mt][nt], ah[mt], bl[nt]);
                    mma8(acc[mt][nt], ah[mt], bh[nt]);
                }
        }
    };

    fill(0, 0);
    asm volatile("cp.async.commit_group;\n");
    for (int t = 0; t < T; t++) {
        if (t + 1 < T) {
            fill(t + 1, (t + 1) & 1);
            asm volatile("cp.async.commit_group;\n");
            asm volatile("cp.async.wait_group 1;\n");
        } else {
            asm volatile("cp.async.wait_group 0;\n");
        }
        __syncthreads();
        compute(t & 1);
        __syncthreads();
    }

    // ---- epilogue
#pragma unroll
    for (int mt = 0; mt < 2; mt++) {
        const int mr = m0 + wm * 32 + mt * 16 + (lane >> 2);
#pragma unroll
        for (int nt = 0; nt < 8; nt++) {
            const int nc = n0 + wn * 64 + nt * 8 + (lane & 3) * 2;
            float v0 = acc[mt][nt][0], v1 = acc[mt][nt][1];
            float v2 = acc[mt][nt][2], v3 = acc[mt][nt][3];
            if (SPLITK) {
                if (nc < N) {
                    atomicAdd(&C[(size_t)mr * ldc + nc], v0);
                    atomicAdd(&C[(size_t)mr * ldc + nc + 1], v1);
                    atomicAdd(&C[(size_t)(mr + 8) * ldc + nc], v2);
                    atomicAdd(&C[(size_t)(mr + 8) * ldc + nc + 1], v3);
                }
            } else {
                if (EPI >= 1) {
                    const float b0 = bias[nc], b1 = bias[nc + 1];
                    v0 += b0; v1 += b1; v2 += b0; v3 += b1;
                }
                if (EPI == 2) {
                    v0 = softplusf(v0); v1 = softplusf(v1);
                    v2 = softplusf(v2); v3 = softplusf(v3);
                }
                *reinterpret_cast<float2*>(&C[(size_t)mr * ldc + nc])       = make_float2(v0, v1);
                *reinterpret_cast<float2*>(&C[(size_t)(mr + 8) * ldc + nc]) = make_float2(v2, v3);
            }
        }
    }
}

__global__ void zero_kernel(float* __restrict__ p, int n) {
    int i = blockIdx.x * blockDim.x + threadIdx.x;
    if (i < n) p[i] = 0.f;
}

// ---------------- conv-shift + silu ----------------
__global__ void __launch_bounds__(256)
conv_kernel(const float* __restrict__ rnn, const float* __restrict__ xz,
            const float* __restrict__ conv_w, const float* __restrict__ conv_b,
            float* __restrict__ out_states, float* __restrict__ xc)
{
    const size_t idx = (size_t)blockIdx.x * 256 + threadIdx.x;
    const int b = (int)(idx / D_INNER);
    const int d = (int)(idx % D_INNER);
    const size_t srow = (size_t)b * (D_INNER * STATE_W) + (size_t)d * STATE_W;

    float4 cs = *reinterpret_cast<const float4*>(rnn + srow);
    float xi = xz[(size_t)b * (2 * D_INNER) + d];
    float4 w = *reinterpret_cast<const float4*>(conv_w + d * 4);

    float v = cs.y * w.x + cs.z * w.y + cs.w * w.z + xi * w.w + conv_b[d];
    xc[idx] = siluf(v);
    *reinterpret_cast<float4*>(out_states + srow) = make_float4(cs.y, cs.z, cs.w, xi);
}

// ---------------- SSM state update + gating ----------------
__global__ void __launch_bounds__(256)
ssm_kernel(const float* __restrict__ rnn, const float* __restrict__ xz,
           const float* __restrict__ xdb, const float* __restrict__ dt_,
           const float* __restrict__ xc_, const float* __restrict__ A_log,
           const float* __restrict__ Dp,
           float* __restrict__ out_states, float* __restrict__ y_)
{
    const int b = blockIdx.y;
    const int d = blockIdx.x * 256 + threadIdx.x;

    __shared__ float sBC[32];
    if (threadIdx.x < 32) sBC[threadIdx.x] = xdb[(size_t)b * XDB_COLS + DT_RANK + threadIdx.x];
    __syncthreads();

    const size_t bd = (size_t)b * D_INNER + d;
    const float dt = dt_[bd];
    const float xc = xc_[bd];
    const float z = xz[(size_t)b * (2 * D_INNER) + D_INNER + d];
    const float dtxc = dt * xc;

    const size_t srow = (size_t)b * (D_INNER * STATE_W) + (size_t)d * STATE_W;
    const float4* ss = reinterpret_cast<const float4*>(rnn + srow + D_CONV);
    float4* os = reinterpret_cast<float4*>(out_states + srow + D_CONV);
    const float4* Al = reinterpret_cast<const float4*>(A_log + d * D_STATE);

    float y = 0.f;
#pragma unroll
    for (int q = 0; q < 4; q++) {
        float4 s = ss[q];
        float4 a = Al[q];
        float sn[4] = {s.x, s.y, s.z, s.w};
        float an[4] = {a.x, a.y, a.z, a.w};
        float on[4];
#pragma unroll
        for (int i = 0; i < 4; i++) {
            const int n = q * 4 + i;
            const float dA = __expf(-dt * __expf(an[i]));
            const float sv = sn[i] * dA + dtxc * sBC[n];
            on[i] = sv;
            y += sv * sBC[16 + n];
        }
        os[q] = make_float4(on[0], on[1], on[2], on[3]);
    }
    y += Dp[d] * xc;
    y *= siluf(z);
    y_[bd] = y;
}

// ---------------- launch ----------------
static void split(const float* p, uint32_t* hi, uint32_t* lo, int n) {
    int n4 = n / 4;
    split_kernel<<<(n4 + 255) / 256, 256>>>(p, hi, lo, n4);
}

extern "C" void kernel_launch(void* const* d_in, const int* in_sizes, int n_in,
                              void* d_out, int out_size)
{
    const float* x          = (const float*)d_in[0];
    const float* rnn        = (const float*)d_in[1];
    const float* w_inp      = (const float*)d_in[2];
    const float* b_inp      = (const float*)d_in[3];
    const float* w_outp     = (const float*)d_in[4];
    const float* b_outp     = (const float*)d_in[5];
    const float* in_proj_w  = (const float*)d_in[6];
    const float* conv_w     = (const float*)d_in[7];
    const float* conv_b     = (const float*)d_in[8];
    const float* x_proj_w   = (const float*)d_in[9];
    const float* dt_proj_w  = (const float*)d_in[10];
    const float* dt_proj_b  = (const float*)d_in[11];
    const float* A_log      = (const float*)d_in[12];
    const float* Dp         = (const float*)d_in[13];
    const float* out_proj_w = (const float*)d_in[14];

    float* out = (float*)d_out;
    float* out_states = out + (size_t)BATCH * OUT_SIZE;

    float *p_h, *p_xz, *p_xc, *p_xdb, *p_dt, *p_y, *p_core;
    uint32_t *Ahi, *Alo, *Bhi, *Blo;
    cudaGetSymbolAddress((void**)&p_h,    g_h);
    cudaGetSymbolAddress((void**)&p_xz,   g_xz);
    cudaGetSymbolAddress((void**)&p_xc,   g_xc);
    cudaGetSymbolAddress((void**)&p_xdb,  g_xdb);
    cudaGetSymbolAddress((void**)&p_dt,   g_dt);
    cudaGetSymbolAddress((void**)&p_y,    g_y);
    cudaGetSymbolAddress((void**)&p_core, g_core);
    cudaGetSymbolAddress((void**)&Ahi,    g_Ahi);
    cudaGetSymbolAddress((void**)&Alo,    g_Alo);
    cudaGetSymbolAddress((void**)&Bhi,    g_Bhi);
    cudaGetSymbolAddress((void**)&Blo,    g_Blo);

    const int SM_TB = (2 * (2 * 128 * 36 + 2 * 128 * 36)) * 4;  // 147456
    const int SM_NB = (2 * (2 * 128 * 36 + 2 * 32 * 132)) * 4;  // 141312
    cudaFuncSetAttribute(tgemm2<false, 1, false>, cudaFuncAttributeMaxDynamicSharedMemorySize, SM_NB);
    cudaFuncSetAttribute(tgemm2<true,  0, false>, cudaFuncAttributeMaxDynamicSharedMemorySize, SM_TB);
    cudaFuncSetAttribute(tgemm2<true,  0, true >, cudaFuncAttributeMaxDynamicSharedMemorySize, SM_TB);
    cudaFuncSetAttribute(tgemm2<true,  2, false>, cudaFuncAttributeMaxDynamicSharedMemorySize, SM_TB);

    dim3 blk(256);

    // 1) h = x @ w_inp + b_inp
    split(x, Ahi, Alo, BATCH * IN_SIZE);
    split(w_inp, Bhi, Blo, IN_SIZE * D_MODEL);
    tgemm2<false, 1, false><<<dim3(D_MODEL / 128, BATCH / 128), blk, SM_NB>>>(
        Ahi, Alo, Bhi, Blo, p_h, b_inp, BATCH, D_MODEL, IN_SIZE, IN_SIZE, D_MODEL, D_MODEL);

    // 2) xz = h @ in_proj_w^T
    split(p_h, Ahi, Alo, BATCH * D_MODEL);
    split(in_proj_w, Bhi, Blo, 2 * D_INNER * D_MODEL);
    tgemm2<true, 0, false><<<dim3(2 * D_INNER / 128, BATCH / 128), blk, SM_TB>>>(
        Ahi, Alo, Bhi, Blo, p_xz, nullptr, BATCH, 2 * D_INNER, D_MODEL, D_MODEL, D_MODEL, 2 * D_INNER);

    // 3) conv shift + silu
    conv_kernel<<<(BATCH * D_INNER) / 256, blk>>>(rnn, p_xz, conv_w, conv_b, out_states, p_xc);

    // 4) xdb = xc @ x_proj_w^T  (N=96, split-K=8, tensor)
    zero_kernel<<<(BATCH * XDB_COLS + 255) / 256, blk>>>(p_xdb, BATCH * XDB_COLS);
    split(p_xc, Ahi, Alo, BATCH * D_INNER);
    split(x_proj_w, Bhi, Blo, XDB_COLS * D_INNER);
    tgemm2<true, 0, true><<<dim3(1, BATCH / 128, 8), blk, SM_TB>>>(
        Ahi, Alo, Bhi, Blo, p_xdb, nullptr, BATCH, XDB_COLS, D_INNER, D_INNER, D_INNER, XDB_COLS);

    // 5) dt = softplus(xdb[:, :64] @ dt_proj_w^T + dt_proj_b)
    split(p_xdb, Ahi, Alo, BATCH * XDB_COLS);
    split(dt_proj_w, Bhi, Blo, D_INNER * DT_RANK);
    tgemm2<true, 2, false><<<dim3(D_INNER / 128, BATCH / 128), blk, SM_TB>>>(
        Ahi, Alo, Bhi, Blo, p_dt, dt_proj_b, BATCH, D_INNER, DT_RANK, XDB_COLS, DT_RANK, D_INNER);

    // 6) SSM update + y
    ssm_kernel<<<dim3(D_INNER / 256, BATCH), blk>>>(
        rnn, p_xz, p_xdb, p_dt, p_xc, A_log, Dp, out_states, p_y);

    // 7) core = y @ out_proj_w^T
    split(p_y, Ahi, Alo, BATCH * D_INNER);
    split(out_proj_w, Bhi, Blo, D_MODEL * D_INNER);
    tgemm2<true, 0, false><<<dim3(D_MODEL / 128, BATCH / 128), blk, SM_TB>>>(
        Ahi, Alo, Bhi, Blo, p_core, nullptr, BATCH, D_MODEL, D_INNER, D_INNER, D_INNER, D_MODEL);

    // 8) out = core @ w_outp + b_outp
    split(p_core, Ahi, Alo, BATCH * D_MODEL);
    split(w_outp, Bhi, Blo, D_MODEL * OUT_SIZE);
    tgemm2<false, 1, false><<<dim3(OUT_SIZE / 128, BATCH / 128), blk, SM_NB>>>(
        Ahi, Alo, Bhi, Blo, out, b_outp, BATCH, OUT_SIZE, D_MODEL, D_MODEL, OUT_SIZE, OUT_SIZE);
}

// round 4
// speedup vs baseline: 1.5145x; 1.5145x over previous
#include <cuda_runtime.h>
#include <cuda_bf16.h>
#include <math.h>
#include <stdint.h>

#define D_MODEL   1024
#define D_STATE   16
#define D_CONV    4
#define D_INNER   2048
#define DT_RANK   64
#define IN_SIZE   512
#define OUT_SIZE  512
#define BATCH     2048
#define XDB_COLS  96
#define STATE_W   20

typedef __nv_bfloat16 bf16;

// ---------------- fp32 scratch ----------------
__device__ float g_xz[BATCH * 2 * D_INNER];
__device__ float g_xc[BATCH * D_INNER];
__device__ float g_xdb[BATCH * XDB_COLS];
__device__ float g_dt[BATCH * D_INNER];
// ---------------- bf16 split scratch ----------------
__device__ bf16 g_h_hi[BATCH * D_MODEL],   g_h_lo[BATCH * D_MODEL];
__device__ bf16 g_x_hi[BATCH * IN_SIZE],   g_x_lo[BATCH * IN_SIZE];
__device__ bf16 g_xc_hi[BATCH * D_INNER],  g_xc_lo[BATCH * D_INNER];
__device__ bf16 g_y_hi[BATCH * D_INNER],   g_y_lo[BATCH * D_INNER];
__device__ bf16 g_co_hi[BATCH * D_MODEL],  g_co_lo[BATCH * D_MODEL];
__device__ bf16 g_xdb_hi[BATCH * XDB_COLS], g_xdb_lo[BATCH * XDB_COLS];
__device__ bf16 g_w1_hi[D_MODEL * IN_SIZE],     g_w1_lo[D_MODEL * IN_SIZE];      // w_inp^T
__device__ bf16 g_w2_hi[2 * D_INNER * D_MODEL], g_w2_lo[2 * D_INNER * D_MODEL];  // in_proj
__device__ bf16 g_w4_hi[XDB_COLS * D_INNER],    g_w4_lo[XDB_COLS * D_INNER];     // x_proj
__device__ bf16 g_w5_hi[D_INNER * DT_RANK],     g_w5_lo[D_INNER * DT_RANK];      // dt_proj
__device__ bf16 g_w7_hi[D_MODEL * D_INNER],     g_w7_lo[D_MODEL * D_INNER];      // out_proj
__device__ bf16 g_w8_hi[OUT_SIZE * D_MODEL],    g_w8_lo[OUT_SIZE * D_MODEL];     // w_outp^T

// ---------------- helpers ----------------
__device__ __forceinline__ float softplusf(float x) {
    return (x > 0.f) ? (x + log1pf(__expf(-x))) : log1pf(__expf(x));
}
__device__ __forceinline__ float siluf(float x) {
    return x / (1.f + __expf(-x));
}
__device__ __forceinline__ void bsplit(float v, bf16& h, bf16& l) {
    h = __float2bfloat16_rn(v);
    l = __float2bfloat16_rn(v - __bfloat162float(h));
}
__device__ __forceinline__ void mmabf(float* c, const uint32_t* a, const uint32_t* b) {
    asm volatile(
        "mma.sync.aligned.m16n8k16.row.col.f32.bf16.bf16.f32 "
        "{%0,%1,%2,%3}, {%4,%5,%6,%7}, {%8,%9}, {%0,%1,%2,%3};"
        : "+f"(c[0]), "+f"(c[1]), "+f"(c[2]), "+f"(c[3])
        : "r"(a[0]), "r"(a[1]), "r"(a[2]), "r"(a[3]), "r"(b[0]), "r"(b[1]));
}
__device__ __forceinline__ void cpa16(uint32_t dst, const void* src, bool p) {
    int sz = p ? 16 : 0;
    asm volatile("cp.async.cg.shared.global [%0], [%1], 16, %2;\n"
                 :: "r"(dst), "l"(src), "r"(sz));
}

// ---------------- split pass (same layout) ----------------
__global__ void __launch_bounds__(256)
split_kernel(const float* __restrict__ in, bf16* __restrict__ hi,
             bf16* __restrict__ lo, int n4)
{
    int i = blockIdx.x * 256 + threadIdx.x;
    if (i < n4) {
        float4 v = reinterpret_cast<const float4*>(in)[i];
        bf16 h0, l0, h1, l1, h2, l2, h3, l3;
        bsplit(v.x, h0, l0); bsplit(v.y, h1, l1);
        bsplit(v.z, h2, l2); bsplit(v.w, h3, l3);
        __nv_bfloat162 hA = {h0, h1}, hB = {h2, h3};
        __nv_bfloat162 lA = {l0, l1}, lB = {l2, l3};
        uint2 hu = {*(uint32_t*)&hA, *(uint32_t*)&hB};
        uint2 lu = {*(uint32_t*)&lA, *(uint32_t*)&lB};
        reinterpret_cast<uint2*>(hi)[i] = hu;
        reinterpret_cast<uint2*>(lo)[i] = lu;
    }
}

// ---------------- transpose + split: in K x N fp32 -> out N x K bf16 hi/lo ----------------
__global__ void __launch_bounds__(256)
tsplit_kernel(const float* __restrict__ in, bf16* __restrict__ hi,
              bf16* __restrict__ lo, int K, int N)
{
    __shared__ float t[32][33];
    const int k0 = blockIdx.y * 32, n0 = blockIdx.x * 32;
    const int tx = threadIdx.x & 31, ty = threadIdx.x >> 5;   // 32 x 8
#pragma unroll
    for (int j = ty; j < 32; j += 8)
        t[j][tx] = in[(size_t)(k0 + j) * N + n0 + tx];
    __syncthreads();
#pragma unroll
    for (int j = ty; j < 32; j += 8) {
        float v = t[tx][j];                 // in[k0+tx][n0+j]
        bf16 h, l; bsplit(v, h, l);
        hi[(size_t)(n0 + j) * K + k0 + tx] = h;
        lo[(size_t)(n0 + j) * K + k0 + tx] = l;
    }
}

// ======================================================================
// 2xBF16-split tensor GEMM. C[M,N] = A[M,K] * B^T, A: MxK, B: NxK (both
// bf16 hi/lo, K contiguous). BM=BN=128, BK=64 elems, 256 thr,
// warps 4(m)x2(n), warp tile 32x64. cp.async 2-stage.
// EPI: 0 none, 1 +bias, 2 +bias+softplus. SPLITK: atomicAdd+guards.
// WSPLIT: write bf16 hi/lo result instead of fp32.
// ======================================================================
#define TG_SMEM (2 * 4 * 128 * 36 * 4)   // 147456 B

template<int EPI, bool SPLITK, bool WSPLIT>
__global__ void __launch_bounds__(256, 1)
bgemm(const bf16* __restrict__ Ahi, const bf16* __restrict__ Alo,
      const bf16* __restrict__ Bhi, const bf16* __restrict__ Blo,
      float* __restrict__ C, bf16* __restrict__ Chi, bf16* __restrict__ Clo,
      const float* __restrict__ bias,
      int M, int N, int K, int lda, int ldb, int ldc)
{
    extern __shared__ uint32_t smbuf[];
    constexpr int TSZ = 128 * 36;          // one tile (uint32 pairs)
    constexpr int STAGE = 4 * TSZ;

    const uint32_t* A32h = reinterpret_cast<const uint32_t*>(Ahi);
    const uint32_t* A32l = reinterpret_cast<const uint32_t*>(Alo);
    const uint32_t* B32h = reinterpret_cast<const uint32_t*>(Bhi);
    const uint32_t* B32l = reinterpret_cast<const uint32_t*>(Blo);
    const int ldap = lda >> 1, ldbp = ldb >> 1;

    const int tid  = threadIdx.x;
    const int lane = tid & 31;
    const int warp = tid >> 5;
    const int wm   = warp & 3;
    const int wn   = warp >> 2;
    const int m0   = blockIdx.y * 128;
    const int n0   = blockIdx.x * 128;
    const int Kc   = SPLITK ? (K / gridDim.z) : K;
    const int k0b  = SPLITK ? (blockIdx.z * Kc) : 0;
    const int T    = Kc / 64;

    const int lr = tid >> 3;              // 0..31 row
    const int lc = (tid & 7) * 4;         // pair col 0..28

    float acc[2][8][4];
#pragma unroll
    for (int i = 0; i < 2; i++)
#pragma unroll
        for (int j = 0; j < 8; j++)
#pragma unroll
            for (int q = 0; q < 4; q++) acc[i][j][q] = 0.f;

    auto fill = [&](int t, int st) {
        uint32_t* Ah = smbuf + st * STAGE;
        uint32_t* Al = Ah + TSZ;
        uint32_t* Bh = Al + TSZ;
        uint32_t* Bl = Bh + TSZ;
        const int kp0 = (k0b + t * 64) >> 1;   // pair offset
#pragma unroll
        for (int it = 0; it < 4; it++) {
            const int row = lr + it * 32;
            const size_t g = (size_t)(m0 + row) * ldap + kp0 + lc;
            cpa16((uint32_t)__cvta_generic_to_shared(&Ah[row * 36 + lc]), A32h + g, true);
            cpa16((uint32_t)__cvta_generic_to_shared(&Al[row * 36 + lc]), A32l + g, true);
        }
#pragma unroll
        for (int it = 0; it < 4; it++) {
            const int row = lr + it * 32;
            const bool p = SPLITK ? ((n0 + row) < N) : true;
            const size_t g = (size_t)(n0 + row) * ldbp + kp0 + lc;
            cpa16((uint32_t)__cvta_generic_to_shared(&Bh[row * 36 + lc]), B32h + g, p);
            cpa16((uint32_t)__cvta_generic_to_shared(&Bl[row * 36 + lc]), B32l + g, p);
        }
    };

    auto compute = [&](int st) {
        uint32_t* Ah = smbuf + st * STAGE;
        uint32_t* Al = Ah + TSZ;
        uint32_t* Bh = Al + TSZ;
        uint32_t* Bl = Bh + TSZ;
#pragma unroll
        for (int ks = 0; ks < 32; ks += 8) {   // pair units; slice = 16 bf16
            uint32_t ah[2][4], al[2][4];
#pragma unroll
            for (int mt = 0; mt < 2; mt++) {
                const int mr = wm * 32 + mt * 16 + (lane >> 2);
                const int kc = ks + (lane & 3);
                ah[mt][0] = Ah[mr * 36 + kc];
                ah[mt][1] = Ah[(mr + 8) * 36 + kc];
                ah[mt][2] = Ah[mr * 36 + kc + 4];
                ah[mt][3] = Ah[(mr + 8) * 36 + kc + 4];
                al[mt][0] = Al[mr * 36 + kc];
                al[mt][1] = Al[(mr + 8) * 36 + kc];
                al[mt][2] = Al[mr * 36 + kc + 4];
                al[mt][3] = Al[(mr + 8) * 36 + kc + 4];
            }
            uint32_t bh[8][2], bl[8][2];
#pragma unroll
            for (int nt = 0; nt < 8; nt++) {
                const int nc = wn * 64 + nt * 8 + (lane >> 2);
                const int kc = ks + (lane & 3);
                bh[nt][0] = Bh[nc * 36 + kc];
                bh[nt][1] = Bh[nc * 36 + kc + 4];
                bl[nt][0] = Bl[nc * 36 + kc];
                bl[nt][1] = Bl[nc * 36 + kc + 4];
            }
#pragma unroll
            for (int mt = 0; mt < 2; mt++)
#pragma unroll
                for (int nt = 0; nt < 8; nt++) {
                    mmabf(acc[mt][nt], ah[mt], bl[nt]);   // hi * lo'
                    mmabf(acc[mt][nt], al[mt], bh[nt]);   // lo * hi'
                    mmabf(acc[mt][nt], ah[mt], bh[nt]);   // hi * hi'
                }
        }
    };

    fill(0, 0);
    asm volatile("cp.async.commit_group;\n");
    for (int t = 0; t < T; t++) {
        if (t + 1 < T) {
            fill(t + 1, (t + 1) & 1);
            asm volatile("cp.async.commit_group;\n");
            asm volatile("cp.async.wait_group 1;\n");
        } else {
            asm volatile("cp.async.wait_group 0;\n");
        }
        __syncthreads();
        compute(t & 1);
        __syncthreads();
    }

    // ---- epilogue
#pragma unroll
    for (int mt = 0; mt < 2; mt++) {
        const int mr = m0 + wm * 32 + mt * 16 + (lane >> 2);
#pragma unroll
        for (int nt = 0; nt < 8; nt++) {
            const int nc = n0 + wn * 64 + nt * 8 + (lane & 3) * 2;
            float v0 = acc[mt][nt][0], v1 = acc[mt][nt][1];
            float v2 = acc[mt][nt][2], v3 = acc[mt][nt][3];
            if (SPLITK) {
                if (nc < N) {
                    atomicAdd(&C[(size_t)mr * ldc + nc], v0);
                    atomicAdd(&C[(size_t)mr * ldc + nc + 1], v1);
                    atomicAdd(&C[(size_t)(mr + 8) * ldc + nc], v2);
                    atomicAdd(&C[(size_t)(mr + 8) * ldc + nc + 1], v3);
                }
                continue;
            }
            if (EPI >= 1) {
                const float b0 = bias[nc], b1 = bias[nc + 1];
                v0 += b0; v1 += b1; v2 += b0; v3 += b1;
            }
            if (EPI == 2) {
                v0 = softplusf(v0); v1 = softplusf(v1);
                v2 = softplusf(v2); v3 = softplusf(v3);
            }
            if (WSPLIT) {
                bf16 h0, l0, h1, l1, h2, l2, h3, l3;
                bsplit(v0, h0, l0); bsplit(v1, h1, l1);
                bsplit(v2, h2, l2); bsplit(v3, h3, l3);
                __nv_bfloat162 ha = {h0, h1}, hb = {h2, h3};
                __nv_bfloat162 la = {l0, l1}, lb = {l2, l3};
                *reinterpret_cast<uint32_t*>(&Chi[(size_t)mr * ldc + nc])       = *(uint32_t*)&ha;
                *reinterpret_cast<uint32_t*>(&Chi[(size_t)(mr + 8) * ldc + nc]) = *(uint32_t*)&hb;
                *reinterpret_cast<uint32_t*>(&Clo[(size_t)mr * ldc + nc])       = *(uint32_t*)&la;
                *reinterpret_cast<uint32_t*>(&Clo[(size_t)(mr + 8) * ldc + nc]) = *(uint32_t*)&lb;
            } else {
                *reinterpret_cast<float2*>(&C[(size_t)mr * ldc + nc])       = make_float2(v0, v1);
                *reinterpret_cast<float2*>(&C[(size_t)(mr + 8) * ldc + nc]) = make_float2(v2, v3);
            }
        }
    }
}

__global__ void zero_kernel(float* __restrict__ p, int n) {
    int i = blockIdx.x * blockDim.x + threadIdx.x;
    if (i < n) p[i] = 0.f;
}

// ---------------- conv-shift + silu (writes fp32 + split) ----------------
__global__ void __launch_bounds__(256)
conv_kernel(const float* __restrict__ rnn, const float* __restrict__ xz,
            const float* __restrict__ conv_w, const float* __restrict__ conv_b,
            float* __restrict__ out_states, float* __restrict__ xc,
            bf16* __restrict__ xch, bf16* __restrict__ xcl)
{
    const size_t idx = (size_t)blockIdx.x * 256 + threadIdx.x;
    const int b = (int)(idx / D_INNER);
    const int d = (int)(idx % D_INNER);
    const size_t srow = (size_t)b * (D_INNER * STATE_W) + (size_t)d * STATE_W;

    float4 cs = *reinterpret_cast<const float4*>(rnn + srow);
    float xi = xz[(size_t)b * (2 * D_INNER) + d];
    float4 w = *reinterpret_cast<const float4*>(conv_w + d * 4);

    float v = cs.y * w.x + cs.z * w.y + cs.w * w.z + xi * w.w + conv_b[d];
    float s = siluf(v);
    xc[idx] = s;
    bf16 h, l; bsplit(s, h, l);
    xch[idx] = h; xcl[idx] = l;
    *reinterpret_cast<float4*>(out_states + srow) = make_float4(cs.y, cs.z, cs.w, xi);
}

// ---------------- SSM state update + gating (writes split y) ----------------
__global__ void __launch_bounds__(256)
ssm_kernel(const float* __restrict__ rnn, const float* __restrict__ xz,
           const float* __restrict__ xdb, const float* __restrict__ dt_,
           const float* __restrict__ xc_, const float* __restrict__ A_log,
           const float* __restrict__ Dp,
           float* __restrict__ out_states, bf16* __restrict__ yh, bf16* __restrict__ yl)
{
    const int b = blockIdx.y;
    const int d = blockIdx.x * 256 + threadIdx.x;

    __shared__ float sBC[32];
    if (threadIdx.x < 32) sBC[threadIdx.x] = xdb[(size_t)b * XDB_COLS + DT_RANK + threadIdx.x];
    __syncthreads();

    const size_t bd = (size_t)b * D_INNER + d;
    const float dt = dt_[bd];
    const float xc = xc_[bd];
    const float z = xz[(size_t)b * (2 * D_INNER) + D_INNER + d];
    const float dtxc = dt * xc;

    const size_t srow = (size_t)b * (D_INNER * STATE_W) + (size_t)d * STATE_W;
    const float4* ss = reinterpret_cast<const float4*>(rnn + srow + D_CONV);
    float4* os = reinterpret_cast<float4*>(out_states + srow + D_CONV);
    const float4* Al = reinterpret_cast<const float4*>(A_log + d * D_STATE);

    float y = 0.f;
#pragma unroll
    for (int q = 0; q < 4; q++) {
        float4 s = ss[q];
        float4 a = Al[q];
        float sn[4] = {s.x, s.y, s.z, s.w};
        float an[4] = {a.x, a.y, a.z, a.w};
        float on[4];
#pragma unroll
        for (int i = 0; i < 4; i++) {
            const int n = q * 4 + i;
            const float dA = __expf(-dt * __expf(an[i]));
            const float sv = sn[i] * dA + dtxc * sBC[n];
            on[i] = sv;
            y += sv * sBC[16 + n];
        }
        os[q] = make_float4(on[0], on[1], on[2], on[3]);
    }
    y += Dp[d] * xc;
    y *= siluf(z);
    bf16 h, l; bsplit(y, h, l);
    yh[bd] = h; yl[bd] = l;
}

// ---------------- launch ----------------
#define GETP(sym, var) float* var; cudaGetSymbolAddress((void**)&var, sym)
#define GETB(sym, var) bf16* var; cudaGetSymbolAddress((void**)&var, sym)

extern "C" void kernel_launch(void* const* d_in, const int* in_sizes, int n_in,
                              void* d_out, int out_size)
{
    const float* x          = (const float*)d_in[0];
    const float* rnn        = (const float*)d_in[1];
    const float* w_inp      = (const float*)d_in[2];
    const float* b_inp      = (const float*)d_in[3];
    const float* w_outp     = (const float*)d_in[4];
    const float* b_outp     = (const float*)d_in[5];
    const float* in_proj_w  = (const float*)d_in[6];
    const float* conv_w     = (const float*)d_in[7];
    const float* conv_b     = (const float*)d_in[8];
    const float* x_proj_w   = (const float*)d_in[9];
    const float* dt_proj_w  = (const float*)d_in[10];
    const float* dt_proj_b  = (const float*)d_in[11];
    const float* A_log      = (const float*)d_in[12];
    const float* Dp         = (const float*)d_in[13];
    const float* out_proj_w = (const float*)d_in[14];

    float* out = (float*)d_out;
    float* out_states = out + (size_t)BATCH * OUT_SIZE;

    GETP(g_xz, p_xz);   GETP(g_xc, p_xc);   GETP(g_xdb, p_xdb);  GETP(g_dt, p_dt);
    GETB(g_h_hi, hH);   GETB(g_h_lo, hL);
    GETB(g_x_hi, xH);   GETB(g_x_lo, xL);
    GETB(g_xc_hi, xcH); GETB(g_xc_lo, xcL);
    GETB(g_y_hi, yH);   GETB(g_y_lo, yL);
    GETB(g_co_hi, coH); GETB(g_co_lo, coL);
    GETB(g_xdb_hi, xdH); GETB(g_xdb_lo, xdL);
    GETB(g_w1_hi, w1H); GETB(g_w1_lo, w1L);
    GETB(g_w2_hi, w2H); GETB(g_w2_lo, w2L);
    GETB(g_w4_hi, w4H); GETB(g_w4_lo, w4L);
    GETB(g_w5_hi, w5H); GETB(g_w5_lo, w5L);
    GETB(g_w7_hi, w7H); GETB(g_w7_lo, w7L);
    GETB(g_w8_hi, w8H); GETB(g_w8_lo, w8L);

    cudaFuncSetAttribute(bgemm<0, false, false>, cudaFuncAttributeMaxDynamicSharedMemorySize, TG_SMEM);
    cudaFuncSetAttribute(bgemm<1, false, false>, cudaFuncAttributeMaxDynamicSharedMemorySize, TG_SMEM);
    cudaFuncSetAttribute(bgemm<2, false, false>, cudaFuncAttributeMaxDynamicSharedMemorySize, TG_SMEM);
    cudaFuncSetAttribute(bgemm<0, true,  false>, cudaFuncAttributeMaxDynamicSharedMemorySize, TG_SMEM);
    cudaFuncSetAttribute(bgemm<0, false, true >, cudaFuncAttributeMaxDynamicSharedMemorySize, TG_SMEM);
    cudaFuncSetAttribute(bgemm<1, false, true >, cudaFuncAttributeMaxDynamicSharedMemorySize, TG_SMEM);

    dim3 blk(256);

    // ---- weight / input splits
    split_kernel<<<(BATCH * IN_SIZE / 4 + 255) / 256, blk>>>(x, xH, xL, BATCH * IN_SIZE / 4);
    tsplit_kernel<<<dim3(D_MODEL / 32, IN_SIZE / 32), blk>>>(w_inp, w1H, w1L, IN_SIZE, D_MODEL);
    split_kernel<<<(2 * D_INNER * D_MODEL / 4 + 255) / 256, blk>>>(in_proj_w, w2H, w2L, 2 * D_INNER * D_MODEL / 4);
    split_kernel<<<(XDB_COLS * D_INNER / 4 + 255) / 256, blk>>>(x_proj_w, w4H, w4L, XDB_COLS * D_INNER / 4);
    split_kernel<<<(D_INNER * DT_RANK / 4 + 255) / 256, blk>>>(dt_proj_w, w5H, w5L, D_INNER * DT_RANK / 4);
    split_kernel<<<(D_MODEL * D_INNER / 4 + 255) / 256, blk>>>(out_proj_w, w7H, w7L, D_MODEL * D_INNER / 4);
    tsplit_kernel<<<dim3(OUT_SIZE / 32, D_MODEL / 32), blk>>>(w_outp, w8H, w8L, D_MODEL, OUT_SIZE);

    // 1) h = x @ w_inp + b_inp -> split h   (2048x1024, K=512)
    bgemm<1, false, true><<<dim3(D_MODEL / 128, BATCH / 128), blk, TG_SMEM>>>(
        xH, xL, w1H, w1L, nullptr, hH, hL, b_inp,
        BATCH, D_MODEL, IN_SIZE, IN_SIZE, IN_SIZE, D_MODEL);

    // 2) xz = h @ in_proj_w^T  (2048x4096, K=1024) -> fp32
    bgemm<0, false, false><<<dim3(2 * D_INNER / 128, BATCH / 128), blk, TG_SMEM>>>(
        hH, hL, w2H, w2L, p_xz, nullptr, nullptr, nullptr,
        BATCH, 2 * D_INNER, D_MODEL, D_MODEL, D_MODEL, 2 * D_INNER);

    // 3) conv shift + silu -> xc fp32 + split
    conv_kernel<<<(BATCH * D_INNER) / 256, blk>>>(rnn, p_xz, conv_w, conv_b, out_states, p_xc, xcH, xcL);

    // 4) xdb = xc @ x_proj_w^T  (N=96, K=2048, split-K=8)
    zero_kernel<<<(BATCH * XDB_COLS + 255) / 256, blk>>>(p_xdb, BATCH * XDB_COLS);
    bgemm<0, true, false><<<dim3(1, BATCH / 128, 8), blk, TG_SMEM>>>(
        xcH, xcL, w4H, w4L, p_xdb, nullptr, nullptr, nullptr,
        BATCH, XDB_COLS, D_INNER, D_INNER, D_INNER, XDB_COLS);
    split_kernel<<<(BATCH * XDB_COLS / 4 + 255) / 256, blk>>>(p_xdb, xdH, xdL, BATCH * XDB_COLS / 4);

    // 5) dt = softplus(xdb[:, :64] @ dt_proj_w^T + dt_proj_b)  (2048x2048, K=64)
    bgemm<2, false, false><<<dim3(D_INNER / 128, BATCH / 128), blk, TG_SMEM>>>(
        xdH, xdL, w5H, w5L, p_dt, nullptr, nullptr, dt_proj_b,
        BATCH, D_INNER, DT_RANK, XDB_COLS, DT_RANK, D_INNER);

    // 6) SSM update -> split y
    ssm_kernel<<<dim3(D_INNER / 256, BATCH), blk>>>(
        rnn, p_xz, p_xdb, p_dt, p_xc, A_log, Dp, out_states, yH, yL);

    // 7) core = y @ out_proj_w^T  (2048x1024, K=2048) -> split core
    bgemm<0, false, true><<<dim3(D_MODEL / 128, BATCH / 128), blk, TG_SMEM>>>(
        yH, yL, w7H, w7L, nullptr, coH, coL, nullptr,
        BATCH, D_MODEL, D_INNER, D_INNER, D_INNER, D_MODEL);

    // 8) out = core @ w_outp + b_outp  (2048x512, K=1024)
    bgemm<1, false, false><<<dim3(OUT_SIZE / 128, BATCH / 128), blk, TG_SMEM>>>(
        coH, coL, w8H, w8L, out, nullptr, nullptr, b_outp,
        BATCH, OUT_SIZE, D_MODEL, D_MODEL, D_MODEL, OUT_SIZE);
}